// round 12
// baseline (speedup 1.0000x reference)
#include <cuda_runtime.h>
#include <math.h>
#include <stdint.h>

// ConvPolicy14 nanonet — champion structure + SMEM-first stage 1.
// 4 warps:
//   pre-bar1 : warp0 builds jcat (ghosted) then stage1 from LDS-immediate
//              offsets; warp2 stage2-7 weights + biases + ACT zeroing;
//              warp3 deconv2/3 repack; warp1 atan2/ext stragglers.
//   post-bar1: warp0 stages 2..9; warp1 PD4 first half; warp3 PD4 second half.
//   post-bar2: stage 10 across warps 0+1.

// ---- padded repacked weight offsets (floats, 16B blocks) ----
#define PW2 192    // [4][4][4]  = 64
#define PW3 256    // 64
#define PW4 320    // [3][4][4]  = 48
#define PD1 368    // [4][3][4]  = 48  (transposed from (3,4,3))
#define PD2 416    // [4][8][4]  = 128
#define PD3 544    // 128
#define PD4 672    // [6][16][4] = 384
#define PTOT 1056

// ---- bias/ext SMEM (compact), not zeroed ----
#define BB2  4
#define BB3  8
#define BB4  12
#define BDB1 15
#define BDB2 19
#define BDB3 23
#define BDB4 27
#define BEXT 36
#define BTOT 40

// ---- ghosted activations. rows have 1 ghost col each side ----
#define JG(i,c)   ACT[(i)*9+(c)]          // 12 x 9, valid cols 1..7
#define C1G(i,c)  ACT[108+(i)*9+(c)]      // 4 x 9
#define C2G(i,c)  ACT[144+(i)*9+(c)]      // 4 x 9
#define DSG(i,c)  ACT[180+(i)*5+(c)]      // 4 x 5, valid 1..3
#define C3G(i,c)  ACT[200+(i)*5+(c)]      // 4 x 5
#define DC1G(i,c) ACT[220+(i)*5+(c)]      // 4 x 5
#define DC2G(i,c) ACT[240+(i)*5+(c)]      // 4 x 5
#define DC3G(i,c) ACT[260+(i)*9+(c)]      // 4 x 9 -> 296

__device__ __forceinline__ float ftanh(float v) {
    float r; asm("tanh.approx.f32 %0, %1;" : "=f"(r) : "f"(v)); return r;
}

__global__ void __launch_bounds__(128, 1)
convpolicy14_kernel(
    const float* __restrict__ x,
    const float* __restrict__ w1, const float* __restrict__ b1,
    const float* __restrict__ w2, const float* __restrict__ b2,
    const float* __restrict__ w3, const float* __restrict__ b3,
    const float* __restrict__ w4, const float* __restrict__ b4,
    const float* __restrict__ dw1, const float* __restrict__ db1,
    const float* __restrict__ dw2, const float* __restrict__ db2,
    const float* __restrict__ dw3, const float* __restrict__ db3,
    const float* __restrict__ dw4, const float* __restrict__ db4,
    float* __restrict__ out)
{
    const int tid  = threadIdx.x;
    const int warp = tid >> 5;
    const int t1   = tid & 31;

    __shared__ __align__(16) float PAD[PTOT];
    __shared__ __align__(16) float BIA[BTOT];
    __shared__ __align__(16) float ACT[296];

    if (warp == 0) {
        // zero C1G ghost cols (8 cells) — warp0-owned
        if (t1 < 8) ACT[108 + (t1 >> 1) * 9 + (t1 & 1) * 8] = 0.f;

        // build ghosted jcat (108 cells) — also consumed by stage 10
        for (int idx = t1; idx < 108; idx += 32) {
            int ch = idx / 9, c = idx % 9 - 1;
            float v = 0.f;
            if (c >= 0 && c < 7) {
                int flat = (ch < 6 ? ch : ch - 6) * 7 + c;
                if (flat >= 2)
                    v = (ch < 6) ? __ldg(x + 5 + flat) : __ldg(x + 51 + flat);
            }
            ACT[idx] = v;
        }
        __syncwarp();

        // ---- Stage 1: conv1 (12->4, pad=1, L=7) — LDS immediate offsets ----
        if (t1 < 28) {
            int o = t1 / 7, p = t1 % 7;
            float wv[36];
            #pragma unroll
            for (int j = 0; j < 9; j++)
                *(float4*)&wv[j*4] = __ldg((const float4*)w1 + o*9 + j);
            float a0 = __ldg(b1 + o), a1 = 0.f, a2 = 0.f;
            #pragma unroll
            for (int i = 0; i < 12; i++) {
                a0 += JG(i, p+0) * wv[i*3+0];
                a1 += JG(i, p+1) * wv[i*3+1];
                a2 += JG(i, p+2) * wv[i*3+2];
            }
            C1G(o, p+1) = ftanh(a0 + a1 + a2);
        }
    } else if (warp == 1) {
        // ONLY the ext stragglers pre-bar1 — atan2 starts at cycle 0.
        if (t1 == 0) {
            float qw = __ldg(x+3), qx = __ldg(x+4), qy = __ldg(x+5), qz = __ldg(x+6);
            BIA[BEXT + 0] = atan2f(qz, qw) - atan2f(-qx, qy);
        } else if (t1 == 1) {
            BIA[BDB4 + 5] = __ldg(db4 + 5);
        } else if (t1 == 2) {
            BIA[BEXT + 1] = __ldg(x + 47);
        } else if (t1 == 3) {
            BIA[BEXT + 2] = __ldg(x + 52);
        }
    } else if (warp == 2) {
        if (t1 < 16) {  // conv2, conv3 (o-major)
            {
                float a = __ldg(w2 + t1*3), b = __ldg(w2 + t1*3 + 1), c = __ldg(w2 + t1*3 + 2);
                *(float4*)&PAD[PW2 + t1*4] = make_float4(a, b, c, 0.f);
            }
            {
                float a = __ldg(w3 + t1*3), b = __ldg(w3 + t1*3 + 1), c = __ldg(w3 + t1*3 + 2);
                *(float4*)&PAD[PW3 + t1*4] = make_float4(a, b, c, 0.f);
            }
        }
        if (t1 < 12) {  // conv4 (o-major), deconv1 (transpose (3,4,3) -> [o][i])
            {
                float a = __ldg(w4 + t1*3), b = __ldg(w4 + t1*3 + 1), c = __ldg(w4 + t1*3 + 2);
                *(float4*)&PAD[PW4 + t1*4] = make_float4(a, b, c, 0.f);
            }
            {
                int o = t1 / 3, i = t1 % 3, s = (i*4 + o)*3;
                float a = __ldg(dw1 + s), b = __ldg(dw1 + s + 1), c = __ldg(dw1 + s + 2);
                *(float4*)&PAD[PD1 + t1*4] = make_float4(a, b, c, 0.f);
            }
        }
        // branchless bias gather: BIA[0..31] = b1,b2,b3,b4,db1,db2,db3,db4[0..4]
        {
            const float* s = b1; int off = t1;
            if (t1 >= 4)  { s = b2;  off = t1 - 4;  }
            if (t1 >= 8)  { s = b3;  off = t1 - 8;  }
            if (t1 >= 12) { s = b4;  off = t1 - 12; }
            if (t1 >= 15) { s = db1; off = t1 - 15; }
            if (t1 >= 19) { s = db2; off = t1 - 19; }
            if (t1 >= 23) { s = db3; off = t1 - 23; }
            if (t1 >= 27) { s = db4; off = t1 - 27; }
            BIA[t1] = __ldg(s + off);
        }
        // zero ACT[144..295] (C2G..DC3G incl. ghosts): float4 j = 36..73
        for (int j = 36 + t1; j < 74; j += 32)
            *(float4*)&ACT[j*4] = make_float4(0.f, 0.f, 0.f, 0.f);
    } else {
        {   // deconv2: j=o*8+i, src (8,4,3): s=(i*4+o)*3
            int o = t1 / 8, i = t1 % 8, s = (i*4 + o)*3;
            float a = __ldg(dw2 + s), b = __ldg(dw2 + s + 1), c = __ldg(dw2 + s + 2);
            *(float4*)&PAD[PD2 + t1*4] = make_float4(a, b, c, 0.f);
        }
        {   // deconv3
            int o = t1 / 8, i = t1 % 8, s = (i*4 + o)*3;
            float a = __ldg(dw3 + s), b = __ldg(dw3 + s + 1), c = __ldg(dw3 + s + 2);
            *(float4*)&PAD[PD3 + t1*4] = make_float4(a, b, c, 0.f);
        }
    }
    __syncthreads();   // bar1: stage1 + stage2..9 weights/biases/ext + jcat ready

    if (warp == 0) {
        // ---- Stage 2: conv2 (4->4, pad=1, L=7) ----
        if (t1 < 28) {
            int o = t1 / 7, p = t1 % 7;
            float a0 = BIA[BB2 + o], a1 = 0.f, a2 = 0.f;
            #pragma unroll
            for (int i = 0; i < 4; i++) {
                float4 w = *(const float4*)&PAD[PW2 + (o*4 + i)*4];
                a0 += C1G(i, p+0) * w.x;
                a1 += C1G(i, p+1) * w.y;
                a2 += C1G(i, p+2) * w.z;
            }
            C2G(o, p+1) = ftanh(a0 + a1 + a2);
        }
        __syncwarp();

        // ---- Stage 3: downsample means ----
        if (t1 < 12) {
            int o = t1 / 3, j = t1 % 3;
            DSG(o, j+1) = (C2G(o, 2*j+1) + C2G(o, 2*j+2) + C2G(o, 2*j+3)) * (1.f/3.f);
        }
        __syncwarp();

        // ---- Stage 4: conv3 (4->4, pad=1, L=3) ----
        if (t1 < 12) {
            int o = t1 / 3, p = t1 % 3;
            float a0 = BIA[BB3 + o], a1 = 0.f, a2 = 0.f;
            #pragma unroll
            for (int i = 0; i < 4; i++) {
                float4 w = *(const float4*)&PAD[PW3 + (o*4 + i)*4];
                a0 += DSG(i, p+0) * w.x;
                a1 += DSG(i, p+1) * w.y;
                a2 += DSG(i, p+2) * w.z;
            }
            C3G(o, p+1) = ftanh(a0 + a1 + a2);
        }
        __syncwarp();

        // ---- Stage 5+6 fused: conv4 + ext, then deconv1 ----
        if (t1 < 12) {
            int o = t1 / 3, p = t1 % 3;
            float cv[12];
            #pragma unroll
            for (int i = 0; i < 4; i++) {
                cv[i*3+0] = C3G(i, 1);
                cv[i*3+1] = C3G(i, 2);
                cv[i*3+2] = C3G(i, 3);
            }
            float comb[3];
            #pragma unroll
            for (int j = 0; j < 3; j++) {
                float a0 = BIA[BB4 + j], a1 = 0.f, a2 = 0.f;
                #pragma unroll
                for (int i = 0; i < 4; i++) {
                    float4 w = *(const float4*)&PAD[PW4 + (j*4 + i)*4];
                    a0 += cv[i*3+0] * w.x;
                    a1 += cv[i*3+1] * w.y;
                    a2 += cv[i*3+2] * w.z;
                }
                comb[j] = ftanh(a0 + a1 + a2) + BIA[BEXT + j];
            }
            float acc = BIA[BDB1 + o];
            #pragma unroll
            for (int j = 0; j < 3; j++)
                acc += comb[j] * PAD[PD1 + (o*3 + j)*4 + p];
            DC1G(o, p+1) = ftanh(acc);
        }
        __syncwarp();

        // ---- Stage 7: deconv2 (8->4, pad=1, L=3) ----
        if (t1 < 12) {
            int o = t1 / 3, p = t1 % 3;
            float a0 = BIA[BDB2 + o], a1 = 0.f, a2 = 0.f;
            #pragma unroll
            for (int i = 0; i < 8; i++) {
                float4 w = *(const float4*)&PAD[PD2 + (o*8 + i)*4];
                float v0 = (i < 4) ? DC1G(i, p+2) : C3G(i-4, p+2);
                float v1 = (i < 4) ? DC1G(i, p+1) : C3G(i-4, p+1);
                float v2 = (i < 4) ? DC1G(i, p+0) : C3G(i-4, p+0);
                a0 += v0 * w.x;
                a1 += v1 * w.y;
                a2 += v2 * w.z;
            }
            DC2G(o, p+1) = ftanh(a0 + a1 + a2);
        }
        __syncwarp();

        // ---- Stage 9: deconv3 (8->4, pad=1, L=7) with upsample fused ----
        if (t1 < 28) {
            int o = t1 / 7, p = t1 % 7;
            int cu[3];
            #pragma unroll
            for (int k = 0; k < 3; k++) {
                int t = p - k + 1;
                cu[k] = (t < 0) ? 0 : ((t > 6) ? 4 : ((t < 3) ? 1 : ((t < 5) ? 2 : 3)));
            }
            float a0 = BIA[BDB3 + o], a1 = 0.f, a2 = 0.f;
            #pragma unroll
            for (int i = 0; i < 8; i++) {
                float4 w = *(const float4*)&PAD[PD3 + (o*8 + i)*4];
                float v0 = (i < 4) ? DC2G(i, cu[0]) : C2G(i-4, p+2);
                float v1 = (i < 4) ? DC2G(i, cu[1]) : C2G(i-4, p+1);
                float v2 = (i < 4) ? DC2G(i, cu[2]) : C2G(i-4, p+0);
                a0 += v0 * w.x;
                a1 += v1 * w.y;
                a2 += v2 * w.z;
            }
            DC3G(o, p+1) = ftanh(a0 + a1 + a2);
        }
    } else if (warp == 1) {
        // post-bar1: PD4 first half
        for (int j = t1; j < 48; j += 32) {
            int o = j / 16, i = j % 16, s = (i*6 + o)*3;
            float a = __ldg(dw4 + s), b = __ldg(dw4 + s + 1), c = __ldg(dw4 + s + 2);
            *(float4*)&PAD[PD4 + j*4] = make_float4(a, b, c, 0.f);
        }
    } else if (warp == 3) {
        // post-bar1: PD4 second half
        for (int j = 48 + t1; j < 96; j += 32) {
            int o = j / 16, i = j % 16, s = (i*6 + o)*3;
            float a = __ldg(dw4 + s), b = __ldg(dw4 + s + 1), c = __ldg(dw4 + s + 2);
            *(float4*)&PAD[PD4 + j*4] = make_float4(a, b, c, 0.f);
        }
    }
    __syncthreads();   // bar2: dc3 + PD4 ready (jcat ready since bar1)

    // ---- Stage 10: deconv4 (16->6, pad=1, L=7), linear; out = flat[2:] ----
    if (tid < 42) {
        int o = tid / 7, p = tid % 7;
        float a0 = BIA[BDB4 + o], a1 = 0.f, a2 = 0.f;
        #pragma unroll
        for (int i = 0; i < 16; i++) {
            float4 w = *(const float4*)&PAD[PD4 + (o*16 + i)*4];
            float v0 = (i < 4) ? DC3G(i, p+2) : JG(i-4, p+2);
            float v1 = (i < 4) ? DC3G(i, p+1) : JG(i-4, p+1);
            float v2 = (i < 4) ? DC3G(i, p+0) : JG(i-4, p+0);
            a0 += v0 * w.x;
            a1 += v1 * w.y;
            a2 += v2 * w.z;
        }
        int flat = o * 7 + p;
        if (flat >= 2) out[flat - 2] = (a0 + a1) + a2;
    }
}

extern "C" void kernel_launch(void* const* d_in, const int* in_sizes, int n_in,
                              void* d_out, int out_size) {
    const float* x   = (const float*)d_in[0];
    const float* w1  = (const float*)d_in[1];
    const float* b1  = (const float*)d_in[2];
    const float* w2  = (const float*)d_in[3];
    const float* b2  = (const float*)d_in[4];
    const float* w3  = (const float*)d_in[5];
    const float* b3  = (const float*)d_in[6];
    const float* w4  = (const float*)d_in[7];
    const float* b4  = (const float*)d_in[8];
    const float* dw1 = (const float*)d_in[9];
    const float* db1 = (const float*)d_in[10];
    const float* dw2 = (const float*)d_in[11];
    const float* db2 = (const float*)d_in[12];
    const float* dw3 = (const float*)d_in[13];
    const float* db3 = (const float*)d_in[14];
    const float* dw4 = (const float*)d_in[15];
    const float* db4 = (const float*)d_in[16];
    float* out = (float*)d_out;

    convpolicy14_kernel<<<1, 128>>>(x, w1, b1, w2, b2, w3, b3, w4, b4,
                                    dw1, db1, dw2, db2, dw3, db3, dw4, db4, out);
}

// round 13
// speedup vs baseline: 1.0435x; 1.0435x over previous
#include <cuda_runtime.h>
#include <math.h>
#include <stdint.h>

// ConvPolicy14 nanonet — FINAL champion configuration (round-8).
// 4 warps, work scheduled by consumption time:
//   pre-bar1 : warp0 stage1 (straight from global, LDGs interleaved with FMAs),
//              warp2 stage2-7 weights + biases + ACT zeroing,
//              warp3 deconv2/3 repack, warp1 atan2/ext stragglers.
//   post-bar1: warp0 stages 2..9; warp1 jcat + PD4 first half;
//              warp3 PD4 second half (jcat/PD4 consumed only after bar2).
//   post-bar2: stage 10 across warps 0+1.
// Ghost-zero activation borders (guard-free inner loops); repacked o-major
// weights with 16B padding (one LDS.128 per (o,i) k-triple); MUFU.TANH;
// fused conv4+deconv1; upsample fused into deconv3.

// ---- padded repacked weight offsets (floats, 16B blocks) ----
#define PW2 192    // [4][4][4]  = 64
#define PW3 256    // 64
#define PW4 320    // [3][4][4]  = 48
#define PD1 368    // [4][3][4]  = 48  (transposed from (3,4,3))
#define PD2 416    // [4][8][4]  = 128
#define PD3 544    // 128
#define PD4 672    // [6][16][4] = 384
#define PTOT 1056

// ---- bias/ext SMEM (compact), not zeroed ----
#define BB2  4
#define BB3  8
#define BB4  12
#define BDB1 15
#define BDB2 19
#define BDB3 23
#define BDB4 27
#define BEXT 36
#define BTOT 40

// ---- ghosted activations. rows have 1 ghost col each side ----
#define JG(i,c)   ACT[(i)*9+(c)]          // 12 x 9, valid cols 1..7
#define C1G(i,c)  ACT[108+(i)*9+(c)]      // 4 x 9
#define C2G(i,c)  ACT[144+(i)*9+(c)]      // 4 x 9
#define DSG(i,c)  ACT[180+(i)*5+(c)]      // 4 x 5, valid 1..3
#define C3G(i,c)  ACT[200+(i)*5+(c)]      // 4 x 5
#define DC1G(i,c) ACT[220+(i)*5+(c)]      // 4 x 5
#define DC2G(i,c) ACT[240+(i)*5+(c)]      // 4 x 5
#define DC3G(i,c) ACT[260+(i)*9+(c)]      // 4 x 9 -> 296

__device__ __forceinline__ float ftanh(float v) {
    float r; asm("tanh.approx.f32 %0, %1;" : "=f"(r) : "f"(v)); return r;
}

__global__ void __launch_bounds__(128, 1)
convpolicy14_kernel(
    const float* __restrict__ x,
    const float* __restrict__ w1, const float* __restrict__ b1,
    const float* __restrict__ w2, const float* __restrict__ b2,
    const float* __restrict__ w3, const float* __restrict__ b3,
    const float* __restrict__ w4, const float* __restrict__ b4,
    const float* __restrict__ dw1, const float* __restrict__ db1,
    const float* __restrict__ dw2, const float* __restrict__ db2,
    const float* __restrict__ dw3, const float* __restrict__ db3,
    const float* __restrict__ dw4, const float* __restrict__ db4,
    float* __restrict__ out)
{
    const int tid  = threadIdx.x;
    const int warp = tid >> 5;
    const int t1   = tid & 31;

    __shared__ __align__(16) float PAD[PTOT];
    __shared__ __align__(16) float BIA[BTOT];
    __shared__ __align__(16) float ACT[296];

    if (warp == 0) {
        // zero C1G ghost cols (8 cells) — warp0-owned
        if (t1 < 8) ACT[108 + (t1 >> 1) * 9 + (t1 & 1) * 8] = 0.f;

        // ---- Stage 1, barrier-free: conv1 (12->4, pad=1, L=7) from global ----
        if (t1 < 28) {
            int o = t1 / 7, p = t1 % 7;
            float wv[36];
            #pragma unroll
            for (int j = 0; j < 9; j++)
                *(float4*)&wv[j*4] = __ldg((const float4*)w1 + o*9 + j);
            float a0 = __ldg(b1 + o), a1 = 0.f, a2 = 0.f;
            #pragma unroll
            for (int i = 0; i < 12; i++) {
                #pragma unroll
                for (int k = 0; k < 3; k++) {
                    int q = p + k - 1;
                    float xv = 0.f;
                    if (q >= 0 && q < 7) {
                        int flat = (i < 6 ? i : i - 6) * 7 + q;
                        if (flat >= 2)
                            xv = __ldg(((i < 6) ? (x + 5) : (x + 51)) + flat);
                    }
                    float wk = wv[i*3 + k];
                    if (k == 0) a0 += xv * wk;
                    else if (k == 1) a1 += xv * wk;
                    else a2 += xv * wk;
                }
            }
            C1G(o, p+1) = ftanh(a0 + a1 + a2);
        }
    } else if (warp == 1) {
        // ONLY the ext stragglers pre-bar1 — atan2 starts at cycle 0.
        if (t1 == 0) {
            float qw = __ldg(x+3), qx = __ldg(x+4), qy = __ldg(x+5), qz = __ldg(x+6);
            BIA[BEXT + 0] = atan2f(qz, qw) - atan2f(-qx, qy);
        } else if (t1 == 1) {
            BIA[BDB4 + 5] = __ldg(db4 + 5);
        } else if (t1 == 2) {
            BIA[BEXT + 1] = __ldg(x + 47);
        } else if (t1 == 3) {
            BIA[BEXT + 2] = __ldg(x + 52);
        }
    } else if (warp == 2) {
        if (t1 < 16) {  // conv2, conv3 (o-major)
            {
                float a = __ldg(w2 + t1*3), b = __ldg(w2 + t1*3 + 1), c = __ldg(w2 + t1*3 + 2);
                *(float4*)&PAD[PW2 + t1*4] = make_float4(a, b, c, 0.f);
            }
            {
                float a = __ldg(w3 + t1*3), b = __ldg(w3 + t1*3 + 1), c = __ldg(w3 + t1*3 + 2);
                *(float4*)&PAD[PW3 + t1*4] = make_float4(a, b, c, 0.f);
            }
        }
        if (t1 < 12) {  // conv4 (o-major), deconv1 (transpose (3,4,3) -> [o][i])
            {
                float a = __ldg(w4 + t1*3), b = __ldg(w4 + t1*3 + 1), c = __ldg(w4 + t1*3 + 2);
                *(float4*)&PAD[PW4 + t1*4] = make_float4(a, b, c, 0.f);
            }
            {
                int o = t1 / 3, i = t1 % 3, s = (i*4 + o)*3;
                float a = __ldg(dw1 + s), b = __ldg(dw1 + s + 1), c = __ldg(dw1 + s + 2);
                *(float4*)&PAD[PD1 + t1*4] = make_float4(a, b, c, 0.f);
            }
        }
        // branchless bias gather: BIA[0..31] = b1,b2,b3,b4,db1,db2,db3,db4[0..4]
        {
            const float* s = b1; int off = t1;
            if (t1 >= 4)  { s = b2;  off = t1 - 4;  }
            if (t1 >= 8)  { s = b3;  off = t1 - 8;  }
            if (t1 >= 12) { s = b4;  off = t1 - 12; }
            if (t1 >= 15) { s = db1; off = t1 - 15; }
            if (t1 >= 19) { s = db2; off = t1 - 19; }
            if (t1 >= 23) { s = db3; off = t1 - 23; }
            if (t1 >= 27) { s = db4; off = t1 - 27; }
            BIA[t1] = __ldg(s + off);
        }
        // zero ACT[144..295] (C2G..DC3G incl. ghosts): float4 j = 36..73
        for (int j = 36 + t1; j < 74; j += 32)
            *(float4*)&ACT[j*4] = make_float4(0.f, 0.f, 0.f, 0.f);
    } else {
        {   // deconv2: j=o*8+i, src (8,4,3): s=(i*4+o)*3
            int o = t1 / 8, i = t1 % 8, s = (i*4 + o)*3;
            float a = __ldg(dw2 + s), b = __ldg(dw2 + s + 1), c = __ldg(dw2 + s + 2);
            *(float4*)&PAD[PD2 + t1*4] = make_float4(a, b, c, 0.f);
        }
        {   // deconv3
            int o = t1 / 8, i = t1 % 8, s = (i*4 + o)*3;
            float a = __ldg(dw3 + s), b = __ldg(dw3 + s + 1), c = __ldg(dw3 + s + 2);
            *(float4*)&PAD[PD3 + t1*4] = make_float4(a, b, c, 0.f);
        }
    }
    __syncthreads();   // bar1: stage1 + stage2..9 weights/biases/ext ready

    if (warp == 0) {
        // ---- Stage 2: conv2 (4->4, pad=1, L=7) ----
        if (t1 < 28) {
            int o = t1 / 7, p = t1 % 7;
            float a0 = BIA[BB2 + o], a1 = 0.f, a2 = 0.f;
            #pragma unroll
            for (int i = 0; i < 4; i++) {
                float4 w = *(const float4*)&PAD[PW2 + (o*4 + i)*4];
                a0 += C1G(i, p+0) * w.x;
                a1 += C1G(i, p+1) * w.y;
                a2 += C1G(i, p+2) * w.z;
            }
            C2G(o, p+1) = ftanh(a0 + a1 + a2);
        }
        __syncwarp();

        // ---- Stage 3: downsample means ----
        if (t1 < 12) {
            int o = t1 / 3, j = t1 % 3;
            DSG(o, j+1) = (C2G(o, 2*j+1) + C2G(o, 2*j+2) + C2G(o, 2*j+3)) * (1.f/3.f);
        }
        __syncwarp();

        // ---- Stage 4: conv3 (4->4, pad=1, L=3) ----
        if (t1 < 12) {
            int o = t1 / 3, p = t1 % 3;
            float a0 = BIA[BB3 + o], a1 = 0.f, a2 = 0.f;
            #pragma unroll
            for (int i = 0; i < 4; i++) {
                float4 w = *(const float4*)&PAD[PW3 + (o*4 + i)*4];
                a0 += DSG(i, p+0) * w.x;
                a1 += DSG(i, p+1) * w.y;
                a2 += DSG(i, p+2) * w.z;
            }
            C3G(o, p+1) = ftanh(a0 + a1 + a2);
        }
        __syncwarp();

        // ---- Stage 5+6 fused: conv4 + ext, then deconv1 ----
        if (t1 < 12) {
            int o = t1 / 3, p = t1 % 3;
            float cv[12];
            #pragma unroll
            for (int i = 0; i < 4; i++) {
                cv[i*3+0] = C3G(i, 1);
                cv[i*3+1] = C3G(i, 2);
                cv[i*3+2] = C3G(i, 3);
            }
            float comb[3];
            #pragma unroll
            for (int j = 0; j < 3; j++) {
                float a0 = BIA[BB4 + j], a1 = 0.f, a2 = 0.f;
                #pragma unroll
                for (int i = 0; i < 4; i++) {
                    float4 w = *(const float4*)&PAD[PW4 + (j*4 + i)*4];
                    a0 += cv[i*3+0] * w.x;
                    a1 += cv[i*3+1] * w.y;
                    a2 += cv[i*3+2] * w.z;
                }
                comb[j] = ftanh(a0 + a1 + a2) + BIA[BEXT + j];
            }
            float acc = BIA[BDB1 + o];
            #pragma unroll
            for (int j = 0; j < 3; j++)
                acc += comb[j] * PAD[PD1 + (o*3 + j)*4 + p];
            DC1G(o, p+1) = ftanh(acc);
        }
        __syncwarp();

        // ---- Stage 7: deconv2 (8->4, pad=1, L=3) ----
        if (t1 < 12) {
            int o = t1 / 3, p = t1 % 3;
            float a0 = BIA[BDB2 + o], a1 = 0.f, a2 = 0.f;
            #pragma unroll
            for (int i = 0; i < 8; i++) {
                float4 w = *(const float4*)&PAD[PD2 + (o*8 + i)*4];
                float v0 = (i < 4) ? DC1G(i, p+2) : C3G(i-4, p+2);
                float v1 = (i < 4) ? DC1G(i, p+1) : C3G(i-4, p+1);
                float v2 = (i < 4) ? DC1G(i, p+0) : C3G(i-4, p+0);
                a0 += v0 * w.x;
                a1 += v1 * w.y;
                a2 += v2 * w.z;
            }
            DC2G(o, p+1) = ftanh(a0 + a1 + a2);
        }
        __syncwarp();

        // ---- Stage 9: deconv3 (8->4, pad=1, L=7) with upsample fused ----
        if (t1 < 28) {
            int o = t1 / 7, p = t1 % 7;
            int cu[3];
            #pragma unroll
            for (int k = 0; k < 3; k++) {
                int t = p - k + 1;
                cu[k] = (t < 0) ? 0 : ((t > 6) ? 4 : ((t < 3) ? 1 : ((t < 5) ? 2 : 3)));
            }
            float a0 = BIA[BDB3 + o], a1 = 0.f, a2 = 0.f;
            #pragma unroll
            for (int i = 0; i < 8; i++) {
                float4 w = *(const float4*)&PAD[PD3 + (o*8 + i)*4];
                float v0 = (i < 4) ? DC2G(i, cu[0]) : C2G(i-4, p+2);
                float v1 = (i < 4) ? DC2G(i, cu[1]) : C2G(i-4, p+1);
                float v2 = (i < 4) ? DC2G(i, cu[2]) : C2G(i-4, p+0);
                a0 += v0 * w.x;
                a1 += v1 * w.y;
                a2 += v2 * w.z;
            }
            DC3G(o, p+1) = ftanh(a0 + a1 + a2);
        }
    } else if (warp == 1) {
        // post-bar1: jcat (consumed after bar2) + PD4 first half
        for (int idx = t1; idx < 108; idx += 32) {
            int ch = idx / 9, c = idx % 9 - 1;
            float v = 0.f;
            if (c >= 0 && c < 7) {
                int flat = (ch < 6 ? ch : ch - 6) * 7 + c;
                if (flat >= 2)
                    v = (ch < 6) ? __ldg(x + 5 + flat) : __ldg(x + 51 + flat);
            }
            ACT[idx] = v;
        }
        for (int j = t1; j < 48; j += 32) {
            int o = j / 16, i = j % 16, s = (i*6 + o)*3;
            float a = __ldg(dw4 + s), b = __ldg(dw4 + s + 1), c = __ldg(dw4 + s + 2);
            *(float4*)&PAD[PD4 + j*4] = make_float4(a, b, c, 0.f);
        }
    } else if (warp == 3) {
        // post-bar1: PD4 second half
        for (int j = 48 + t1; j < 96; j += 32) {
            int o = j / 16, i = j % 16, s = (i*6 + o)*3;
            float a = __ldg(dw4 + s), b = __ldg(dw4 + s + 1), c = __ldg(dw4 + s + 2);
            *(float4*)&PAD[PD4 + j*4] = make_float4(a, b, c, 0.f);
        }
    }
    __syncthreads();   // bar2: dc3 + jcat + PD4 ready

    // ---- Stage 10: deconv4 (16->6, pad=1, L=7), linear; out = flat[2:] ----
    if (tid < 42) {
        int o = tid / 7, p = tid % 7;
        float a0 = BIA[BDB4 + o], a1 = 0.f, a2 = 0.f;
        #pragma unroll
        for (int i = 0; i < 16; i++) {
            float4 w = *(const float4*)&PAD[PD4 + (o*16 + i)*4];
            float v0 = (i < 4) ? DC3G(i, p+2) : JG(i-4, p+2);
            float v1 = (i < 4) ? DC3G(i, p+1) : JG(i-4, p+1);
            float v2 = (i < 4) ? DC3G(i, p+0) : JG(i-4, p+0);
            a0 += v0 * w.x;
            a1 += v1 * w.y;
            a2 += v2 * w.z;
        }
        int flat = o * 7 + p;
        if (flat >= 2) out[flat - 2] = (a0 + a1) + a2;
    }
}

extern "C" void kernel_launch(void* const* d_in, const int* in_sizes, int n_in,
                              void* d_out, int out_size) {
    const float* x   = (const float*)d_in[0];
    const float* w1  = (const float*)d_in[1];
    const float* b1  = (const float*)d_in[2];
    const float* w2  = (const float*)d_in[3];
    const float* b2  = (const float*)d_in[4];
    const float* w3  = (const float*)d_in[5];
    const float* b3  = (const float*)d_in[6];
    const float* w4  = (const float*)d_in[7];
    const float* b4  = (const float*)d_in[8];
    const float* dw1 = (const float*)d_in[9];
    const float* db1 = (const float*)d_in[10];
    const float* dw2 = (const float*)d_in[11];
    const float* db2 = (const float*)d_in[12];
    const float* dw3 = (const float*)d_in[13];
    const float* db3 = (const float*)d_in[14];
    const float* dw4 = (const float*)d_in[15];
    const float* db4 = (const float*)d_in[16];
    float* out = (float*)d_out;

    convpolicy14_kernel<<<1, 128>>>(x, w1, b1, w2, b2, w3, b3, w4, b4,
                                    dw1, db1, dw2, db2, dw3, db3, dw4, db4, out);
}